// round 13
// baseline (speedup 1.0000x reference)
#include <cuda_runtime.h>

// Langevin_2439541424651 — 131072 independent 200-step scalar recurrences.
// HBM-bound: ~100MB read + ~301MB write. R11 champion config (scalar,
// 1024x128, plain stores, unroll-8, steps folded) + ONE change: __ldcs on
// the zero-reuse noise stream only, to keep 100MB of dead lines from
// competing with dirty write lines in L2 (store-drain/turnaround theory).
// Stores stay plain — .cs stores were the R3/R4 catastrophe.

#define N_PART 1024
#define DX     128
#define STEPS  200
#define ND     (N_PART * DX)                      // 131072 threads
#define TOT_XT ((long)N_PART * STEPS * DX)

__global__ void __launch_bounds__(128) langevin_kernel(
    const float* __restrict__ x0,      // [N, DX]
    const float* __restrict__ y0,      // [N, DX]
    const float* __restrict__ mean,    // [DX]
    const float* __restrict__ var,     // [DX]
    const float* __restrict__ gammas,  // [STEPS]
    const float* __restrict__ noise,   // [STEPS, N, DX]
    float* __restrict__ x_tot,         // [N, STEPS, DX]
    float* __restrict__ y_tot,
    float* __restrict__ out,
    float* __restrict__ steps_out)     // [N, STEPS]
{
    __shared__ float s_g[STEPS];
    __shared__ float s_s[STEPS];

    for (int k = threadIdx.x; k < STEPS; k += blockDim.x) {
        float g = gammas[k];
        s_g[k] = g;
        s_s[k] = sqrtf(2.0f * g);
    }

    int tid = blockIdx.x * blockDim.x + threadIdx.x;   // 0 .. ND-1

    // Steps tensor [N, STEPS, 1]: coalesced prologue, no tail kernel.
    for (int i = tid; i < N_PART * STEPS; i += ND)
        steps_out[i] = (float)(i % STEPS);

    __syncthreads();

    int d = tid & (DX - 1);
    int n = tid >> 7;

    float x  = x0[tid];
    float yv = y0[tid];
    float m  = mean[d];
    float iv = 1.0f / var[d];

    long base = (long)n * STEPS * DX + d;
    const float* __restrict__ zp = noise + tid;

    // t_old = x - c*(x-m);  x_new = t_old + s*z
    // t_old - t_new = (t_old - x_new) + c*(x_new - m),  c = gamma/var
#pragma unroll 8
    for (int k = 0; k < STEPS; ++k) {
        float g = s_g[k];
        float s = s_s[k];
        float z = __ldcs(zp + (long)k * ND);   // streaming read: evict-first

        float c     = g * iv;
        float t_old = fmaf(-c, x - m, x);
        float xn    = fmaf(s, z, t_old);
        float diff  = fmaf(c, xn - m, t_old - xn);
        x = xn;

        long o = base + (long)k * DX;
        x_tot[o] = xn;     // plain cached stores (proven path)
        y_tot[o] = yv;
        out[o]   = diff;
    }
}

extern "C" void kernel_launch(void* const* d_in, const int* in_sizes, int n_in,
                              void* d_out, int out_size)
{
    const float* x0     = (const float*)d_in[0];
    const float* y0     = (const float*)d_in[1];
    const float* mean   = (const float*)d_in[2];
    const float* var    = (const float*)d_in[3];
    const float* gammas = (const float*)d_in[4];
    const float* noise  = (const float*)d_in[5];

    float* base  = (float*)d_out;
    float* x_tot = base;                 // [N, S, D]
    float* y_tot = base + TOT_XT;
    float* outp  = base + 2 * TOT_XT;
    float* steps = base + 3 * TOT_XT;    // [N, S, 1]

    langevin_kernel<<<ND / 128, 128>>>(x0, y0, mean, var, gammas, noise,
                                       x_tot, y_tot, outp, steps);
}

// round 14
// speedup vs baseline: 1.7785x; 1.7785x over previous
#include <cuda_runtime.h>

// Langevin_2439541424651 — 131072 independent 200-step scalar recurrences.
// HBM-bound: ~100MB read + ~301MB write. CHAMPION CONFIG (R11, 67.8us kernel,
// DRAM 67.8%): scalar threads (max problem parallelism), 1024x128 blocks
// (6.92 CTAs/SM, near-perfect balance), plain cached loads AND stores
// (any .cs hint on this traffic halves achieved DRAM BW on GB300 —
// R3/R4/R13 evidence), unroll-8, steps tensor folded into the prologue.
// Measured plateau 5.2-5.4 TB/s across four structurally different kernels
// = practical HBM3e ceiling for this fine-grained 1R:3W mix.

#define N_PART 1024
#define DX     128
#define STEPS  200
#define ND     (N_PART * DX)                      // 131072 threads
#define TOT_XT ((long)N_PART * STEPS * DX)

__global__ void __launch_bounds__(128) langevin_kernel(
    const float* __restrict__ x0,      // [N, DX]
    const float* __restrict__ y0,      // [N, DX]
    const float* __restrict__ mean,    // [DX]
    const float* __restrict__ var,     // [DX]
    const float* __restrict__ gammas,  // [STEPS]
    const float* __restrict__ noise,   // [STEPS, N, DX]
    float* __restrict__ x_tot,         // [N, STEPS, DX]
    float* __restrict__ y_tot,
    float* __restrict__ out,
    float* __restrict__ steps_out)     // [N, STEPS]
{
    __shared__ float s_g[STEPS];
    __shared__ float s_s[STEPS];

    for (int k = threadIdx.x; k < STEPS; k += blockDim.x) {
        float g = gammas[k];
        s_g[k] = g;
        s_s[k] = sqrtf(2.0f * g);
    }

    int tid = blockIdx.x * blockDim.x + threadIdx.x;   // 0 .. ND-1

    // Steps tensor [N, STEPS, 1]: coalesced prologue, no tail kernel.
    for (int i = tid; i < N_PART * STEPS; i += ND)
        steps_out[i] = (float)(i % STEPS);

    __syncthreads();

    int d = tid & (DX - 1);
    int n = tid >> 7;

    float x  = x0[tid];
    float yv = y0[tid];
    float m  = mean[d];
    float iv = 1.0f / var[d];

    long base = (long)n * STEPS * DX + d;
    const float* __restrict__ zp = noise + tid;

    // t_old = x - c*(x-m);  x_new = t_old + s*z
    // t_old - t_new = (t_old - x_new) + c*(x_new - m),  c = gamma/var
#pragma unroll 8
    for (int k = 0; k < STEPS; ++k) {
        float g = s_g[k];
        float s = s_s[k];
        float z = zp[(long)k * ND];

        float c     = g * iv;
        float t_old = fmaf(-c, x - m, x);
        float xn    = fmaf(s, z, t_old);
        float diff  = fmaf(c, xn - m, t_old - xn);
        x = xn;

        long o = base + (long)k * DX;
        x_tot[o] = xn;
        y_tot[o] = yv;
        out[o]   = diff;
    }
}

extern "C" void kernel_launch(void* const* d_in, const int* in_sizes, int n_in,
                              void* d_out, int out_size)
{
    const float* x0     = (const float*)d_in[0];
    const float* y0     = (const float*)d_in[1];
    const float* mean   = (const float*)d_in[2];
    const float* var    = (const float*)d_in[3];
    const float* gammas = (const float*)d_in[4];
    const float* noise  = (const float*)d_in[5];

    float* base  = (float*)d_out;
    float* x_tot = base;                 // [N, S, D]
    float* y_tot = base + TOT_XT;
    float* outp  = base + 2 * TOT_XT;
    float* steps = base + 3 * TOT_XT;    // [N, S, 1]

    langevin_kernel<<<ND / 128, 128>>>(x0, y0, mean, var, gammas, noise,
                                       x_tot, y_tot, outp, steps);
}

// round 15
// speedup vs baseline: 1.7832x; 1.0026x over previous
#include <cuda_runtime.h>

// Langevin_2439541424651 — 131072 independent 200-step scalar recurrences.
// HBM-bound: ~100MB read + ~301MB write. Champion config (R11/R14): scalar
// threads, 1024x128 blocks (6.92 CTAs/SM), plain cached loads AND stores
// (any .cs hint halves achieved DRAM BW on GB300 — R3/R4/R13), steps tensor
// folded into the prologue. This round's single variable: unroll 8 -> 16
// (no reg clamp; 885 thr/SM leaves ~74 regs/thread free) to lengthen the
// scheduling window and smooth bursty DRAM demand.
// Measured plateau 5.1-5.4 TB/s across four kernel shapes = practical
// HBM3e ceiling for this fine-grained 1R:3W mix.

#define N_PART 1024
#define DX     128
#define STEPS  200
#define ND     (N_PART * DX)                      // 131072 threads
#define TOT_XT ((long)N_PART * STEPS * DX)

__global__ void __launch_bounds__(128) langevin_kernel(
    const float* __restrict__ x0,      // [N, DX]
    const float* __restrict__ y0,      // [N, DX]
    const float* __restrict__ mean,    // [DX]
    const float* __restrict__ var,     // [DX]
    const float* __restrict__ gammas,  // [STEPS]
    const float* __restrict__ noise,   // [STEPS, N, DX]
    float* __restrict__ x_tot,         // [N, STEPS, DX]
    float* __restrict__ y_tot,
    float* __restrict__ out,
    float* __restrict__ steps_out)     // [N, STEPS]
{
    __shared__ float s_g[STEPS];
    __shared__ float s_s[STEPS];

    for (int k = threadIdx.x; k < STEPS; k += blockDim.x) {
        float g = gammas[k];
        s_g[k] = g;
        s_s[k] = sqrtf(2.0f * g);
    }

    int tid = blockIdx.x * blockDim.x + threadIdx.x;   // 0 .. ND-1

    // Steps tensor [N, STEPS, 1]: coalesced prologue, no tail kernel.
    for (int i = tid; i < N_PART * STEPS; i += ND)
        steps_out[i] = (float)(i % STEPS);

    __syncthreads();

    int d = tid & (DX - 1);
    int n = tid >> 7;

    float x  = x0[tid];
    float yv = y0[tid];
    float m  = mean[d];
    float iv = 1.0f / var[d];

    long base = (long)n * STEPS * DX + d;
    const float* __restrict__ zp = noise + tid;

    // t_old = x - c*(x-m);  x_new = t_old + s*z
    // t_old - t_new = (t_old - x_new) + c*(x_new - m),  c = gamma/var
#pragma unroll 16
    for (int k = 0; k < STEPS; ++k) {
        float g = s_g[k];
        float s = s_s[k];
        float z = zp[(long)k * ND];

        float c     = g * iv;
        float t_old = fmaf(-c, x - m, x);
        float xn    = fmaf(s, z, t_old);
        float diff  = fmaf(c, xn - m, t_old - xn);
        x = xn;

        long o = base + (long)k * DX;
        x_tot[o] = xn;
        y_tot[o] = yv;
        out[o]   = diff;
    }
}

extern "C" void kernel_launch(void* const* d_in, const int* in_sizes, int n_in,
                              void* d_out, int out_size)
{
    const float* x0     = (const float*)d_in[0];
    const float* y0     = (const float*)d_in[1];
    const float* mean   = (const float*)d_in[2];
    const float* var    = (const float*)d_in[3];
    const float* gammas = (const float*)d_in[4];
    const float* noise  = (const float*)d_in[5];

    float* base  = (float*)d_out;
    float* x_tot = base;                 // [N, S, D]
    float* y_tot = base + TOT_XT;
    float* outp  = base + 2 * TOT_XT;
    float* steps = base + 3 * TOT_XT;    // [N, S, 1]

    langevin_kernel<<<ND / 128, 128>>>(x0, y0, mean, var, gammas, noise,
                                       x_tot, y_tot, outp, steps);
}